// round 4
// baseline (speedup 1.0000x reference)
#include <cuda_runtime.h>
#include <cuda_fp16.h>
#include <cstdint>

#define B_  16
#define Q_  256
#define K_  256
#define H_  256
#define DV_ 256

__device__ float g_qp[B_ * Q_ * H_];
__device__ float g_kp[B_ * K_ * H_];
__device__ float g_scores[B_ * Q_ * K_];

__device__ __forceinline__ __half2 tanh2_h(__half2 x) {
    __half2 y;
    asm("tanh.approx.f16x2 %0, %1;"
        : "=r"(*reinterpret_cast<unsigned*>(&y))
        : "r"(*reinterpret_cast<const unsigned*>(&x)));
    return y;
}

// ---------------------------------------------------------------------------
// Kernel 1: projection GEMM  C[M,256] = A[M,256] * W[256,256]^T
// Double-buffered smem + register prefetch. One sync per K-tile.
// blockIdx.z: 0 -> queries/W_q -> g_qp ; 1 -> keys/W_k -> g_kp
// ---------------------------------------------------------------------------
__global__ __launch_bounds__(256) void proj_gemm(const float* __restrict__ Aq,
                                                 const float* __restrict__ Wq,
                                                 const float* __restrict__ Ak,
                                                 const float* __restrict__ Wk) {
    constexpr int BM = 64, BN = 64, BK = 32;
    __shared__ float As[2][BK][BM + 4];
    __shared__ float Bs[2][BK][BN + 4];

    const float* A;
    const float* W;
    float* C;
    if (blockIdx.z == 0) { A = Aq; W = Wq; C = g_qp; }
    else                 { A = Ak; W = Wk; C = g_kp; }

    const int tid = threadIdx.x;
    const int m0 = blockIdx.y * BM;
    const int n0 = blockIdx.x * BN;
    const int ty = tid >> 4;
    const int tx = tid & 15;
    const int lr = tid >> 3;        // 0..31
    const int lc = (tid & 7) * 4;   // 0,4,...,28

    float acc[4][4];
#pragma unroll
    for (int i = 0; i < 4; i++)
#pragma unroll
        for (int j = 0; j < 4; j++) acc[i][j] = 0.0f;

    float4 ra0, ra1, rb0, rb1;

    auto ldg = [&](int kt) {
        ra0 = *(const float4*)&A[(m0 + lr) * H_ + kt + lc];
        ra1 = *(const float4*)&A[(m0 + lr + 32) * H_ + kt + lc];
        rb0 = *(const float4*)&W[(n0 + lr) * H_ + kt + lc];
        rb1 = *(const float4*)&W[(n0 + lr + 32) * H_ + kt + lc];
    };
    auto sts = [&](int buf) {
        As[buf][lc + 0][lr] = ra0.x; As[buf][lc + 1][lr] = ra0.y;
        As[buf][lc + 2][lr] = ra0.z; As[buf][lc + 3][lr] = ra0.w;
        As[buf][lc + 0][lr + 32] = ra1.x; As[buf][lc + 1][lr + 32] = ra1.y;
        As[buf][lc + 2][lr + 32] = ra1.z; As[buf][lc + 3][lr + 32] = ra1.w;
        Bs[buf][lc + 0][lr] = rb0.x; Bs[buf][lc + 1][lr] = rb0.y;
        Bs[buf][lc + 2][lr] = rb0.z; Bs[buf][lc + 3][lr] = rb0.w;
        Bs[buf][lc + 0][lr + 32] = rb1.x; Bs[buf][lc + 1][lr + 32] = rb1.y;
        Bs[buf][lc + 2][lr + 32] = rb1.z; Bs[buf][lc + 3][lr + 32] = rb1.w;
    };

    ldg(0);
    sts(0);
    __syncthreads();

#pragma unroll
    for (int it = 0; it < H_ / BK; it++) {
        const int buf = it & 1;
        if (it < H_ / BK - 1) ldg((it + 1) * BK);

#pragma unroll
        for (int kk = 0; kk < BK; kk++) {
            float a[4], b[4];
#pragma unroll
            for (int i = 0; i < 4; i++) a[i] = As[buf][kk][ty * 4 + i];
#pragma unroll
            for (int j = 0; j < 4; j++) b[j] = Bs[buf][kk][tx * 4 + j];
#pragma unroll
            for (int i = 0; i < 4; i++)
#pragma unroll
                for (int j = 0; j < 4; j++) acc[i][j] += a[i] * b[j];
        }

        if (it < H_ / BK - 1) sts(buf ^ 1);
        __syncthreads();
    }

#pragma unroll
    for (int i = 0; i < 4; i++) {
        float4 v;
        v.x = acc[i][0]; v.y = acc[i][1]; v.z = acc[i][2]; v.w = acc[i][3];
        *(float4*)&C[(m0 + ty * 4 + i) * H_ + n0 + tx * 4] = v;
    }
}

// ---------------------------------------------------------------------------
// Kernel 2: scores[b,q,k] = sum_h w_v[h] * tanh(qp+kp)   (f16x2 MUFU)
// ---------------------------------------------------------------------------
__global__ __launch_bounds__(256) void scores_f16(const float* __restrict__ wv) {
    const int b = blockIdx.z;
    const int q0 = blockIdx.y * 64;
    const int k0 = blockIdx.x * 64;

    __shared__ __half2 qs[64][17];
    __shared__ __half2 ks[64][17];
    __shared__ __half2 sw2[128];

    const int tid = threadIdx.x;
    if (tid < 128) sw2[tid] = __floats2half2_rn(wv[2 * tid], wv[2 * tid + 1]);

    const int ty = tid >> 4;
    const int tx = tid & 15;
    const int lr = tid >> 3;
    const int lc = (tid & 7) * 4;

    const float* qb = g_qp + (b * Q_ + q0) * H_;
    const float* kb = g_kp + (b * K_ + k0) * H_;

    float facc[4][4];
#pragma unroll
    for (int i = 0; i < 4; i++)
#pragma unroll
        for (int j = 0; j < 4; j++) facc[i][j] = 0.f;

    for (int hc = 0; hc < H_; hc += 32) {
        __syncthreads();
        {
            float4 a0 = *(const float4*)&qb[lr * H_ + hc + lc];
            float4 a1 = *(const float4*)&qb[(lr + 32) * H_ + hc + lc];
            float4 c0 = *(const float4*)&kb[lr * H_ + hc + lc];
            float4 c1 = *(const float4*)&kb[(lr + 32) * H_ + hc + lc];
            qs[lr][lc / 2]          = __floats2half2_rn(a0.x, a0.y);
            qs[lr][lc / 2 + 1]      = __floats2half2_rn(a0.z, a0.w);
            qs[lr + 32][lc / 2]     = __floats2half2_rn(a1.x, a1.y);
            qs[lr + 32][lc / 2 + 1] = __floats2half2_rn(a1.z, a1.w);
            ks[lr][lc / 2]          = __floats2half2_rn(c0.x, c0.y);
            ks[lr][lc / 2 + 1]      = __floats2half2_rn(c0.z, c0.w);
            ks[lr + 32][lc / 2]     = __floats2half2_rn(c1.x, c1.y);
            ks[lr + 32][lc / 2 + 1] = __floats2half2_rn(c1.z, c1.w);
        }
        __syncthreads();

#pragma unroll
        for (int g = 0; g < 4; g++) {
            __half2 cacc[4][4];
            const __half2 z2 = __float2half2_rn(0.f);
#pragma unroll
            for (int i = 0; i < 4; i++)
#pragma unroll
                for (int j = 0; j < 4; j++) cacc[i][j] = z2;

#pragma unroll
            for (int s = 0; s < 4; s++) {
                const int h2 = g * 4 + s;
                __half2 q2[4], k2[4];
#pragma unroll
                for (int i = 0; i < 4; i++) q2[i] = qs[ty * 4 + i][h2];
#pragma unroll
                for (int j = 0; j < 4; j++) k2[j] = ks[tx * 4 + j][h2];
                const __half2 w2 = sw2[(hc >> 1) + h2];
#pragma unroll
                for (int i = 0; i < 4; i++)
#pragma unroll
                    for (int j = 0; j < 4; j++) {
                        __half2 t = tanh2_h(__hadd2(q2[i], k2[j]));
                        cacc[i][j] = __hfma2(t, w2, cacc[i][j]);
                    }
            }
#pragma unroll
            for (int i = 0; i < 4; i++)
#pragma unroll
                for (int j = 0; j < 4; j++) {
                    float2 f = __half22float2(cacc[i][j]);
                    facc[i][j] += f.x + f.y;
                }
        }
    }

    float* sbase = g_scores + (b * Q_ + q0 + ty * 4) * K_ + k0 + tx * 4;
#pragma unroll
    for (int i = 0; i < 4; i++)
        *(float4*)&sbase[i * K_] = make_float4(facc[i][0], facc[i][1], facc[i][2], facc[i][3]);
}

// ---------------------------------------------------------------------------
// Kernel 3: fused softmax + AV.
// Block: 32 q-rows x 128 dv-cols. Softmax 32 rows into smem, then pipelined
// GEMM over V (double-buffered smem, register prefetch).
// Thread tile: 2 rows x 8 cols (two contiguous 4-col groups).
// ---------------------------------------------------------------------------
__global__ __launch_bounds__(256) void softmax_av(const float* __restrict__ V,
                                                  float* __restrict__ out) {
    const int b = blockIdx.y;
    const int q0 = (blockIdx.x >> 1) * 32;
    const int c0 = (blockIdx.x & 1) * 128;

    __shared__ __align__(16) float sattn[32][260];
    __shared__ __align__(16) float vs[2][32][132];

    const int tid = threadIdx.x;
    const int w = tid >> 5;
    const int lane = tid & 31;

    // ---- softmax: warp w -> rows w, w+8, w+16, w+24 ----
#pragma unroll
    for (int i = 0; i < 4; i++) {
        const int r = w + 8 * i;
        const float* srow = g_scores + (b * Q_ + q0 + r) * K_;
        float v[8];
        float mx = -1e30f;
#pragma unroll
        for (int j = 0; j < 8; j++) {
            v[j] = srow[lane + 32 * j];
            mx = fmaxf(mx, v[j]);
        }
#pragma unroll
        for (int off = 16; off; off >>= 1)
            mx = fmaxf(mx, __shfl_xor_sync(0xffffffffu, mx, off));
        float s = 0.f;
#pragma unroll
        for (int j = 0; j < 8; j++) {
            v[j] = __expf(v[j] - mx);
            s += v[j];
        }
#pragma unroll
        for (int off = 16; off; off >>= 1)
            s += __shfl_xor_sync(0xffffffffu, s, off);
        const float inv = 1.0f / s;
#pragma unroll
        for (int j = 0; j < 8; j++) sattn[r][lane + 32 * j] = v[j] * inv;
    }

    // ---- AV: pipelined GEMM ----
    const int ty = tid >> 4;        // 0..15 -> rows ty*2, ty*2+1
    const int tx = tid & 15;        // 0..15 -> cols tx*4 and 64+tx*4
    const int vr = tid >> 3;        // 0..31 V-row within chunk
    const int vc = (tid & 7) * 16;  // 0..112

    float4 rv0, rv1, rv2, rv3;
    auto ldgv = [&](int kc) {
        const float* src = V + (size_t)(b * K_ + kc * 32 + vr) * DV_ + c0 + vc;
        rv0 = *(const float4*)&src[0];
        rv1 = *(const float4*)&src[4];
        rv2 = *(const float4*)&src[8];
        rv3 = *(const float4*)&src[12];
    };
    auto stsv = [&](int buf) {
        *(float4*)&vs[buf][vr][vc + 0]  = rv0;
        *(float4*)&vs[buf][vr][vc + 4]  = rv1;
        *(float4*)&vs[buf][vr][vc + 8]  = rv2;
        *(float4*)&vs[buf][vr][vc + 12] = rv3;
    };

    float acc[2][8];
#pragma unroll
    for (int r = 0; r < 2; r++)
#pragma unroll
        for (int j = 0; j < 8; j++) acc[r][j] = 0.f;

    ldgv(0);
    stsv(0);
    __syncthreads();   // also covers sattn visibility

#pragma unroll
    for (int kc = 0; kc < 8; kc++) {
        const int buf = kc & 1;
        if (kc < 7) ldgv(kc + 1);

#pragma unroll
        for (int kk = 0; kk < 32; kk++) {
            float a0 = sattn[ty * 2 + 0][kc * 32 + kk];
            float a1 = sattn[ty * 2 + 1][kc * 32 + kk];
            float4 b0 = *(const float4*)&vs[buf][kk][tx * 4];
            float4 b1 = *(const float4*)&vs[buf][kk][64 + tx * 4];
            const float* bp0 = (const float*)&b0;
            const float* bp1 = (const float*)&b1;
#pragma unroll
            for (int j = 0; j < 4; j++) {
                acc[0][j]     += a0 * bp0[j];
                acc[1][j]     += a1 * bp0[j];
                acc[0][4 + j] += a0 * bp1[j];
                acc[1][4 + j] += a1 * bp1[j];
            }
        }

        if (kc < 7) stsv(buf ^ 1);
        __syncthreads();
    }

#pragma unroll
    for (int r = 0; r < 2; r++) {
        float* orow = &out[(size_t)(b * Q_ + q0 + ty * 2 + r) * DV_ + c0];
        *(float4*)&orow[tx * 4]      = make_float4(acc[r][0], acc[r][1], acc[r][2], acc[r][3]);
        *(float4*)&orow[64 + tx * 4] = make_float4(acc[r][4], acc[r][5], acc[r][6], acc[r][7]);
    }
}

// ---------------------------------------------------------------------------
extern "C" void kernel_launch(void* const* d_in, const int* in_sizes, int n_in,
                              void* d_out, int out_size) {
    const float* queries = (const float*)d_in[0];
    const float* keys    = (const float*)d_in[1];
    const float* values  = (const float*)d_in[2];
    const float* W_q     = (const float*)d_in[3];
    const float* W_k     = (const float*)d_in[4];
    const float* w_v     = (const float*)d_in[5];
    float* out = (float*)d_out;

    dim3 gproj(H_ / 64, (B_ * Q_) / 64, 2);
    proj_gemm<<<gproj, 256>>>(queries, W_q, keys, W_k);

    dim3 gscores(K_ / 64, Q_ / 64, B_);
    scores_f16<<<gscores, 256>>>(w_v);

    dim3 gav(2 * (Q_ / 32), B_);
    softmax_av<<<gav, 256>>>(values, out);
}

// round 5
// speedup vs baseline: 1.0201x; 1.0201x over previous
#include <cuda_runtime.h>
#include <cuda_fp16.h>
#include <cstdint>

#define B_  16
#define Q_  256
#define K_  256
#define H_  256
#define DV_ 256

__device__ float g_qp[B_ * Q_ * H_];
__device__ float g_kp[B_ * K_ * H_];
__device__ float g_scores[B_ * Q_ * K_];

__device__ __forceinline__ __half2 tanh2_h(__half2 x) {
    __half2 y;
    asm("tanh.approx.f16x2 %0, %1;"
        : "=r"(*reinterpret_cast<unsigned*>(&y))
        : "r"(*reinterpret_cast<const unsigned*>(&x)));
    return y;
}

// ---------------------------------------------------------------------------
// Kernel 1: projection GEMM  C[M,256] = A[M,256] * W[256,256]^T
// EXACT R1 version (measured ~11us/launch). sel==0 -> g_qp, sel==1 -> g_kp.
// ---------------------------------------------------------------------------
__global__ __launch_bounds__(256) void proj_gemm(const float* __restrict__ A,
                                                 const float* __restrict__ W,
                                                 int sel) {
    constexpr int BM = 64, BN = 64, BK = 32;
    __shared__ float As[BK][BM + 4];
    __shared__ float Bs[BK][BN + 4];

    float* __restrict__ C = sel ? g_kp : g_qp;

    const int tid = threadIdx.x;
    const int m0 = blockIdx.y * BM;
    const int n0 = blockIdx.x * BN;
    const int ty = tid >> 4;
    const int tx = tid & 15;

    float acc[4][4];
#pragma unroll
    for (int i = 0; i < 4; i++)
#pragma unroll
        for (int j = 0; j < 4; j++) acc[i][j] = 0.0f;

    const int lr = tid >> 3;
    const int lc = (tid & 7) * 4;

    for (int kt = 0; kt < H_; kt += BK) {
        float4 a0 = *(const float4*)&A[(m0 + lr) * H_ + kt + lc];
        float4 a1 = *(const float4*)&A[(m0 + lr + 32) * H_ + kt + lc];
        float4 b0 = *(const float4*)&W[(n0 + lr) * H_ + kt + lc];
        float4 b1 = *(const float4*)&W[(n0 + lr + 32) * H_ + kt + lc];

        As[lc + 0][lr] = a0.x; As[lc + 1][lr] = a0.y;
        As[lc + 2][lr] = a0.z; As[lc + 3][lr] = a0.w;
        As[lc + 0][lr + 32] = a1.x; As[lc + 1][lr + 32] = a1.y;
        As[lc + 2][lr + 32] = a1.z; As[lc + 3][lr + 32] = a1.w;
        Bs[lc + 0][lr] = b0.x; Bs[lc + 1][lr] = b0.y;
        Bs[lc + 2][lr] = b0.z; Bs[lc + 3][lr] = b0.w;
        Bs[lc + 0][lr + 32] = b1.x; Bs[lc + 1][lr + 32] = b1.y;
        Bs[lc + 2][lr + 32] = b1.z; Bs[lc + 3][lr + 32] = b1.w;

        __syncthreads();

#pragma unroll
        for (int kk = 0; kk < BK; kk++) {
            float a[4], b[4];
#pragma unroll
            for (int i = 0; i < 4; i++) a[i] = As[kk][ty * 4 + i];
#pragma unroll
            for (int j = 0; j < 4; j++) b[j] = Bs[kk][tx * 4 + j];
#pragma unroll
            for (int i = 0; i < 4; i++)
#pragma unroll
                for (int j = 0; j < 4; j++) acc[i][j] += a[i] * b[j];
        }
        __syncthreads();
    }

#pragma unroll
    for (int i = 0; i < 4; i++) {
        float4 v;
        v.x = acc[i][0]; v.y = acc[i][1]; v.z = acc[i][2]; v.w = acc[i][3];
        *(float4*)&C[(m0 + ty * 4 + i) * H_ + n0 + tx * 4] = v;
    }
}

// ---------------------------------------------------------------------------
// Kernel 2: scores[b,q,k] = sum_h w_v[h] * tanh(qp+kp)   (f16x2 MUFU)
// R3/R4 version — tiles converted to half2 once at load; inner loop is
// HADD2 + tanh.approx.f16x2 + HFMA2 only.
// ---------------------------------------------------------------------------
__global__ __launch_bounds__(256) void scores_f16(const float* __restrict__ wv) {
    const int b = blockIdx.z;
    const int q0 = blockIdx.y * 64;
    const int k0 = blockIdx.x * 64;

    __shared__ __half2 qs[64][17];
    __shared__ __half2 ks[64][17];
    __shared__ __half2 sw2[128];

    const int tid = threadIdx.x;
    if (tid < 128) sw2[tid] = __floats2half2_rn(wv[2 * tid], wv[2 * tid + 1]);

    const int ty = tid >> 4;
    const int tx = tid & 15;
    const int lr = tid >> 3;
    const int lc = (tid & 7) * 4;

    const float* qb = g_qp + (b * Q_ + q0) * H_;
    const float* kb = g_kp + (b * K_ + k0) * H_;

    float facc[4][4];
#pragma unroll
    for (int i = 0; i < 4; i++)
#pragma unroll
        for (int j = 0; j < 4; j++) facc[i][j] = 0.f;

    for (int hc = 0; hc < H_; hc += 32) {
        __syncthreads();
        {
            float4 a0 = *(const float4*)&qb[lr * H_ + hc + lc];
            float4 a1 = *(const float4*)&qb[(lr + 32) * H_ + hc + lc];
            float4 c0 = *(const float4*)&kb[lr * H_ + hc + lc];
            float4 c1 = *(const float4*)&kb[(lr + 32) * H_ + hc + lc];
            qs[lr][lc / 2]          = __floats2half2_rn(a0.x, a0.y);
            qs[lr][lc / 2 + 1]      = __floats2half2_rn(a0.z, a0.w);
            qs[lr + 32][lc / 2]     = __floats2half2_rn(a1.x, a1.y);
            qs[lr + 32][lc / 2 + 1] = __floats2half2_rn(a1.z, a1.w);
            ks[lr][lc / 2]          = __floats2half2_rn(c0.x, c0.y);
            ks[lr][lc / 2 + 1]      = __floats2half2_rn(c0.z, c0.w);
            ks[lr + 32][lc / 2]     = __floats2half2_rn(c1.x, c1.y);
            ks[lr + 32][lc / 2 + 1] = __floats2half2_rn(c1.z, c1.w);
        }
        __syncthreads();

#pragma unroll
        for (int g = 0; g < 4; g++) {
            __half2 cacc[4][4];
            const __half2 z2 = __float2half2_rn(0.f);
#pragma unroll
            for (int i = 0; i < 4; i++)
#pragma unroll
                for (int j = 0; j < 4; j++) cacc[i][j] = z2;

#pragma unroll
            for (int s = 0; s < 4; s++) {
                const int h2 = g * 4 + s;
                __half2 q2[4], k2[4];
#pragma unroll
                for (int i = 0; i < 4; i++) q2[i] = qs[ty * 4 + i][h2];
#pragma unroll
                for (int j = 0; j < 4; j++) k2[j] = ks[tx * 4 + j][h2];
                const __half2 w2 = sw2[(hc >> 1) + h2];
#pragma unroll
                for (int i = 0; i < 4; i++)
#pragma unroll
                    for (int j = 0; j < 4; j++) {
                        __half2 t = tanh2_h(__hadd2(q2[i], k2[j]));
                        cacc[i][j] = __hfma2(t, w2, cacc[i][j]);
                    }
            }
#pragma unroll
            for (int i = 0; i < 4; i++)
#pragma unroll
                for (int j = 0; j < 4; j++) {
                    float2 f = __half22float2(cacc[i][j]);
                    facc[i][j] += f.x + f.y;
                }
        }
    }

    float* sbase = g_scores + (b * Q_ + q0 + ty * 4) * K_ + k0 + tx * 4;
#pragma unroll
    for (int i = 0; i < 4; i++)
        *(float4*)&sbase[i * K_] = make_float4(facc[i][0], facc[i][1], facc[i][2], facc[i][3]);
}

// ---------------------------------------------------------------------------
// Kernel 3: fused row-softmax + out = attn @ values  — EXACT R1 version
// (measured 44.2us). Block = 8 q-rows, thread-per-output-column.
// ---------------------------------------------------------------------------
__global__ __launch_bounds__(256) void softmax_av(const float* __restrict__ V,
                                                  float* __restrict__ out) {
    const int b = blockIdx.y;
    const int q0 = blockIdx.x * 8;

    __shared__ float sattn[8][256];

    const int tid = threadIdx.x;
    const int w = tid >> 5;
    const int lane = tid & 31;

    const float* srow = g_scores + (b * Q_ + q0 + w) * K_;
    float vals[8];
    float mx = -1e30f;
#pragma unroll
    for (int i = 0; i < 8; i++) {
        vals[i] = srow[lane + i * 32];
        mx = fmaxf(mx, vals[i]);
    }
#pragma unroll
    for (int off = 16; off; off >>= 1)
        mx = fmaxf(mx, __shfl_xor_sync(0xffffffffu, mx, off));
    float sum = 0.f;
#pragma unroll
    for (int i = 0; i < 8; i++) {
        vals[i] = __expf(vals[i] - mx);
        sum += vals[i];
    }
#pragma unroll
    for (int off = 16; off; off >>= 1)
        sum += __shfl_xor_sync(0xffffffffu, sum, off);
    float inv = 1.0f / sum;
#pragma unroll
    for (int i = 0; i < 8; i++) sattn[w][lane + i * 32] = vals[i] * inv;

    __syncthreads();

    const float* vb = V + b * K_ * DV_;
    const int c = tid;
    float acc[8];
#pragma unroll
    for (int r = 0; r < 8; r++) acc[r] = 0.f;

    for (int k4 = 0; k4 < K_ / 4; k4++) {
        int k = k4 * 4;
        float v0 = vb[(k + 0) * DV_ + c];
        float v1 = vb[(k + 1) * DV_ + c];
        float v2 = vb[(k + 2) * DV_ + c];
        float v3 = vb[(k + 3) * DV_ + c];
#pragma unroll
        for (int r = 0; r < 8; r++) {
            float4 p = *(const float4*)&sattn[r][k];
            acc[r] += p.x * v0 + p.y * v1 + p.z * v2 + p.w * v3;
        }
    }

#pragma unroll
    for (int r = 0; r < 8; r++)
        out[(b * Q_ + q0 + r) * DV_ + c] = acc[r];
}

// ---------------------------------------------------------------------------
extern "C" void kernel_launch(void* const* d_in, const int* in_sizes, int n_in,
                              void* d_out, int out_size) {
    const float* queries = (const float*)d_in[0];
    const float* keys    = (const float*)d_in[1];
    const float* values  = (const float*)d_in[2];
    const float* W_q     = (const float*)d_in[3];
    const float* W_k     = (const float*)d_in[4];
    const float* w_v     = (const float*)d_in[5];
    float* out = (float*)d_out;

    dim3 gproj(H_ / 64, (B_ * Q_) / 64);
    proj_gemm<<<gproj, 256>>>(queries, W_q, 0);
    proj_gemm<<<gproj, 256>>>(keys,    W_k, 1);

    dim3 gscores(K_ / 64, Q_ / 64, B_);
    scores_f16<<<gscores, 256>>>(w_v);

    dim3 gav(Q_ / 8, B_);
    softmax_av<<<gav, 256>>>(values, out);
}

// round 6
// speedup vs baseline: 1.0657x; 1.0446x over previous
#include <cuda_runtime.h>
#include <cuda_fp16.h>
#include <cstdint>

#define B_  16
#define Q_  256
#define K_  256
#define H_  256
#define DV_ 256

__device__ float g_qp[B_ * Q_ * H_];
__device__ float g_kp[B_ * K_ * H_];
__device__ float g_scores[B_ * Q_ * K_];

__device__ __forceinline__ float tanh_fast(float x) {
    float y;
    asm("tanh.approx.f32 %0, %1;" : "=f"(y) : "f"(x));
    return y;
}

// ---------------------------------------------------------------------------
// Kernel 1: projection GEMM  C[M,256] = A[M,256] * W[256,256]^T
// EXACT R1 version (~11us/launch). sel==0 -> g_qp, sel==1 -> g_kp.
// ---------------------------------------------------------------------------
__global__ __launch_bounds__(256) void proj_gemm(const float* __restrict__ A,
                                                 const float* __restrict__ W,
                                                 int sel) {
    constexpr int BM = 64, BN = 64, BK = 32;
    __shared__ float As[BK][BM + 4];
    __shared__ float Bs[BK][BN + 4];

    float* __restrict__ C = sel ? g_kp : g_qp;

    const int tid = threadIdx.x;
    const int m0 = blockIdx.y * BM;
    const int n0 = blockIdx.x * BN;
    const int ty = tid >> 4;
    const int tx = tid & 15;

    float acc[4][4];
#pragma unroll
    for (int i = 0; i < 4; i++)
#pragma unroll
        for (int j = 0; j < 4; j++) acc[i][j] = 0.0f;

    const int lr = tid >> 3;
    const int lc = (tid & 7) * 4;

    for (int kt = 0; kt < H_; kt += BK) {
        float4 a0 = *(const float4*)&A[(m0 + lr) * H_ + kt + lc];
        float4 a1 = *(const float4*)&A[(m0 + lr + 32) * H_ + kt + lc];
        float4 b0 = *(const float4*)&W[(n0 + lr) * H_ + kt + lc];
        float4 b1 = *(const float4*)&W[(n0 + lr + 32) * H_ + kt + lc];

        As[lc + 0][lr] = a0.x; As[lc + 1][lr] = a0.y;
        As[lc + 2][lr] = a0.z; As[lc + 3][lr] = a0.w;
        As[lc + 0][lr + 32] = a1.x; As[lc + 1][lr + 32] = a1.y;
        As[lc + 2][lr + 32] = a1.z; As[lc + 3][lr + 32] = a1.w;
        Bs[lc + 0][lr] = b0.x; Bs[lc + 1][lr] = b0.y;
        Bs[lc + 2][lr] = b0.z; Bs[lc + 3][lr] = b0.w;
        Bs[lc + 0][lr + 32] = b1.x; Bs[lc + 1][lr + 32] = b1.y;
        Bs[lc + 2][lr + 32] = b1.z; Bs[lc + 3][lr + 32] = b1.w;

        __syncthreads();

#pragma unroll
        for (int kk = 0; kk < BK; kk++) {
            float a[4], b[4];
#pragma unroll
            for (int i = 0; i < 4; i++) a[i] = As[kk][ty * 4 + i];
#pragma unroll
            for (int j = 0; j < 4; j++) b[j] = Bs[kk][tx * 4 + j];
#pragma unroll
            for (int i = 0; i < 4; i++)
#pragma unroll
                for (int j = 0; j < 4; j++) acc[i][j] += a[i] * b[j];
        }
        __syncthreads();
    }

#pragma unroll
    for (int i = 0; i < 4; i++) {
        float4 v;
        v.x = acc[i][0]; v.y = acc[i][1]; v.z = acc[i][2]; v.w = acc[i][3];
        *(float4*)&C[(m0 + ty * 4 + i) * H_ + n0 + tx * 4] = v;
    }
}

// ---------------------------------------------------------------------------
// Kernel 2: scores — EXACT R1 fp32 MUFU version (measured at the MUFU floor).
// ---------------------------------------------------------------------------
__global__ __launch_bounds__(256) void scores_kernel(const float* __restrict__ wv) {
    const int b = blockIdx.z;
    const int q0 = blockIdx.y * 32;
    const int k0 = blockIdx.x * 32;

    __shared__ float qs[32][33];
    __shared__ float ks[32][33];
    __shared__ float ws[H_];

    const int tid = threadIdx.x;
    ws[tid] = wv[tid];

    const int ty = tid >> 4;
    const int tx = tid & 15;

    const float* qbase = g_qp + (b * Q_ + q0) * H_;
    const float* kbase = g_kp + (b * K_ + k0) * H_;

    float a00 = 0.f, a01 = 0.f, a10 = 0.f, a11 = 0.f;

    const int lr = tid >> 5;
    const int lc = tid & 31;

    for (int hc = 0; hc < H_; hc += 32) {
        __syncthreads();
#pragma unroll
        for (int rr = 0; rr < 4; rr++) {
            int row = lr + rr * 8;
            qs[row][lc] = qbase[row * H_ + hc + lc];
            ks[row][lc] = kbase[row * H_ + hc + lc];
        }
        __syncthreads();

#pragma unroll
        for (int hh = 0; hh < 32; hh++) {
            float w = ws[hc + hh];
            float qv0 = qs[ty * 2 + 0][hh];
            float qv1 = qs[ty * 2 + 1][hh];
            float kv0 = ks[tx * 2 + 0][hh];
            float kv1 = ks[tx * 2 + 1][hh];
            a00 += w * tanh_fast(qv0 + kv0);
            a01 += w * tanh_fast(qv0 + kv1);
            a10 += w * tanh_fast(qv1 + kv0);
            a11 += w * tanh_fast(qv1 + kv1);
        }
    }

    float* sbase = g_scores + (b * Q_ + q0) * K_ + k0;
    sbase[(ty * 2 + 0) * K_ + tx * 2 + 0] = a00;
    sbase[(ty * 2 + 0) * K_ + tx * 2 + 1] = a01;
    sbase[(ty * 2 + 1) * K_ + tx * 2 + 0] = a10;
    sbase[(ty * 2 + 1) * K_ + tx * 2 + 1] = a11;
}

// ---------------------------------------------------------------------------
// Kernel 3: fused softmax + AV — NEW: 32 rows x 256 cols per block,
// thread tile 8 rows x 4 cols, V via coalesced LDG.128 (L1-reused 4x).
// ---------------------------------------------------------------------------
__global__ __launch_bounds__(256) void softmax_av(const float* __restrict__ V,
                                                  float* __restrict__ out) {
    const int b = blockIdx.y;
    const int q0 = blockIdx.x * 32;

    __shared__ __align__(16) float sp[32][260];   // normalized attn, padded

    const int tid = threadIdx.x;
    const int w = tid >> 5;
    const int lane = tid & 31;

    // ---- softmax: warp w handles rows 4w..4w+3 ----
#pragma unroll
    for (int j = 0; j < 4; j++) {
        const int r = w * 4 + j;
        const float* srow = g_scores + (b * Q_ + q0 + r) * K_;
        float v[8];
        float mx = -1e30f;
#pragma unroll
        for (int i = 0; i < 8; i++) {
            v[i] = srow[lane + 32 * i];
            mx = fmaxf(mx, v[i]);
        }
#pragma unroll
        for (int off = 16; off; off >>= 1)
            mx = fmaxf(mx, __shfl_xor_sync(0xffffffffu, mx, off));
        float s = 0.f;
#pragma unroll
        for (int i = 0; i < 8; i++) {
            v[i] = __expf(v[i] - mx);
            s += v[i];
        }
#pragma unroll
        for (int off = 16; off; off >>= 1)
            s += __shfl_xor_sync(0xffffffffu, s, off);
        const float inv = 1.0f / s;
#pragma unroll
        for (int i = 0; i < 8; i++) sp[r][lane + 32 * i] = v[i] * inv;
    }

    __syncthreads();

    // ---- AV: thread = rows ty*8..ty*8+7, cols c0..c0+3 ----
    const int ty = tid >> 6;            // 0..3
    const int c0 = (tid & 63) * 4;      // 0..252

    const float* vb = V + (size_t)b * K_ * DV_;

    float4 acc[8];
#pragma unroll
    for (int i = 0; i < 8; i++) acc[i] = make_float4(0.f, 0.f, 0.f, 0.f);

    const int r0 = ty * 8;

    for (int k = 0; k < K_; k += 4) {
        float4 a4[8];
#pragma unroll
        for (int i = 0; i < 8; i++)
            a4[i] = *(const float4*)&sp[r0 + i][k];

#pragma unroll
        for (int kk = 0; kk < 4; kk++) {
            float4 v4 = *(const float4*)&vb[(size_t)(k + kk) * DV_ + c0];
#pragma unroll
            for (int i = 0; i < 8; i++) {
                float a = ((const float*)&a4[i])[kk];
                acc[i].x += a * v4.x;
                acc[i].y += a * v4.y;
                acc[i].z += a * v4.z;
                acc[i].w += a * v4.w;
            }
        }
    }

#pragma unroll
    for (int i = 0; i < 8; i++)
        *(float4*)&out[(size_t)(b * Q_ + q0 + r0 + i) * DV_ + c0] = acc[i];
}

// ---------------------------------------------------------------------------
extern "C" void kernel_launch(void* const* d_in, const int* in_sizes, int n_in,
                              void* d_out, int out_size) {
    const float* queries = (const float*)d_in[0];
    const float* keys    = (const float*)d_in[1];
    const float* values  = (const float*)d_in[2];
    const float* W_q     = (const float*)d_in[3];
    const float* W_k     = (const float*)d_in[4];
    const float* w_v     = (const float*)d_in[5];
    float* out = (float*)d_out;

    dim3 gproj(H_ / 64, (B_ * Q_) / 64);
    proj_gemm<<<gproj, 256>>>(queries, W_q, 0);
    proj_gemm<<<gproj, 256>>>(keys,    W_k, 1);

    dim3 gscores(K_ / 32, Q_ / 32, B_);
    scores_kernel<<<gscores, 256>>>(w_v);

    dim3 gav(Q_ / 32, B_);
    softmax_av<<<gav, 256>>>(values, out);
}

// round 7
// speedup vs baseline: 1.1486x; 1.0778x over previous
#include <cuda_runtime.h>
#include <cstdint>

#define B_  16
#define Q_  256
#define K_  256
#define H_  256
#define DV_ 256

__device__ float g_qp[B_ * Q_ * H_];
__device__ float g_kp[B_ * K_ * H_];
__device__ float g_scores[B_ * Q_ * K_];

__device__ __forceinline__ float tanh_fast(float x) {
    float y;
    asm("tanh.approx.f32 %0, %1;" : "=f"(y) : "f"(x));
    return y;
}

// ---------------------------------------------------------------------------
// Kernel 1: projection GEMM  C[M,256] = A[M,256] * W[256,256]^T  (R1 exact)
// ---------------------------------------------------------------------------
__global__ __launch_bounds__(256) void proj_gemm(const float* __restrict__ A,
                                                 const float* __restrict__ W,
                                                 int sel) {
    constexpr int BM = 64, BN = 64, BK = 32;
    __shared__ float As[BK][BM + 4];
    __shared__ float Bs[BK][BN + 4];

    float* __restrict__ C = sel ? g_kp : g_qp;

    const int tid = threadIdx.x;
    const int m0 = blockIdx.y * BM;
    const int n0 = blockIdx.x * BN;
    const int ty = tid >> 4;
    const int tx = tid & 15;

    float acc[4][4];
#pragma unroll
    for (int i = 0; i < 4; i++)
#pragma unroll
        for (int j = 0; j < 4; j++) acc[i][j] = 0.0f;

    const int lr = tid >> 3;
    const int lc = (tid & 7) * 4;

    for (int kt = 0; kt < H_; kt += BK) {
        float4 a0 = *(const float4*)&A[(m0 + lr) * H_ + kt + lc];
        float4 a1 = *(const float4*)&A[(m0 + lr + 32) * H_ + kt + lc];
        float4 b0 = *(const float4*)&W[(n0 + lr) * H_ + kt + lc];
        float4 b1 = *(const float4*)&W[(n0 + lr + 32) * H_ + kt + lc];

        As[lc + 0][lr] = a0.x; As[lc + 1][lr] = a0.y;
        As[lc + 2][lr] = a0.z; As[lc + 3][lr] = a0.w;
        As[lc + 0][lr + 32] = a1.x; As[lc + 1][lr + 32] = a1.y;
        As[lc + 2][lr + 32] = a1.z; As[lc + 3][lr + 32] = a1.w;
        Bs[lc + 0][lr] = b0.x; Bs[lc + 1][lr] = b0.y;
        Bs[lc + 2][lr] = b0.z; Bs[lc + 3][lr] = b0.w;
        Bs[lc + 0][lr + 32] = b1.x; Bs[lc + 1][lr + 32] = b1.y;
        Bs[lc + 2][lr + 32] = b1.z; Bs[lc + 3][lr + 32] = b1.w;

        __syncthreads();

#pragma unroll
        for (int kk = 0; kk < BK; kk++) {
            float a[4], b[4];
#pragma unroll
            for (int i = 0; i < 4; i++) a[i] = As[kk][ty * 4 + i];
#pragma unroll
            for (int j = 0; j < 4; j++) b[j] = Bs[kk][tx * 4 + j];
#pragma unroll
            for (int i = 0; i < 4; i++)
#pragma unroll
                for (int j = 0; j < 4; j++) acc[i][j] += a[i] * b[j];
        }
        __syncthreads();
    }

#pragma unroll
    for (int i = 0; i < 4; i++) {
        float4 v;
        v.x = acc[i][0]; v.y = acc[i][1]; v.z = acc[i][2]; v.w = acc[i][3];
        *(float4*)&C[(m0 + ty * 4 + i) * H_ + n0 + tx * 4] = v;
    }
}

// ---------------------------------------------------------------------------
// Kernel 2: scores — R1 fp32 MUFU version (at the MUFU floor).
// ---------------------------------------------------------------------------
__global__ __launch_bounds__(256) void scores_kernel(const float* __restrict__ wv) {
    const int b = blockIdx.z;
    const int q0 = blockIdx.y * 32;
    const int k0 = blockIdx.x * 32;

    __shared__ float qs[32][33];
    __shared__ float ks[32][33];
    __shared__ float ws[H_];

    const int tid = threadIdx.x;
    ws[tid] = wv[tid];

    const int ty = tid >> 4;
    const int tx = tid & 15;

    const float* qbase = g_qp + (b * Q_ + q0) * H_;
    const float* kbase = g_kp + (b * K_ + k0) * H_;

    float a00 = 0.f, a01 = 0.f, a10 = 0.f, a11 = 0.f;

    const int lr = tid >> 5;
    const int lc = tid & 31;

    for (int hc = 0; hc < H_; hc += 32) {
        __syncthreads();
#pragma unroll
        for (int rr = 0; rr < 4; rr++) {
            int row = lr + rr * 8;
            qs[row][lc] = qbase[row * H_ + hc + lc];
            ks[row][lc] = kbase[row * H_ + hc + lc];
        }
        __syncthreads();

#pragma unroll
        for (int hh = 0; hh < 32; hh++) {
            float w = ws[hc + hh];
            float qv0 = qs[ty * 2 + 0][hh];
            float qv1 = qs[ty * 2 + 1][hh];
            float kv0 = ks[tx * 2 + 0][hh];
            float kv1 = ks[tx * 2 + 1][hh];
            a00 += w * tanh_fast(qv0 + kv0);
            a01 += w * tanh_fast(qv0 + kv1);
            a10 += w * tanh_fast(qv1 + kv0);
            a11 += w * tanh_fast(qv1 + kv1);
        }
    }

    float* sbase = g_scores + (b * Q_ + q0) * K_ + k0;
    sbase[(ty * 2 + 0) * K_ + tx * 2 + 0] = a00;
    sbase[(ty * 2 + 0) * K_ + tx * 2 + 1] = a01;
    sbase[(ty * 2 + 1) * K_ + tx * 2 + 0] = a10;
    sbase[(ty * 2 + 1) * K_ + tx * 2 + 1] = a11;
}

// ---------------------------------------------------------------------------
// Kernel 3: in-place row softmax over g_scores. One warp per row.
// ---------------------------------------------------------------------------
__global__ __launch_bounds__(256) void softmax_inplace() {
    const int row = blockIdx.x * 8 + (threadIdx.x >> 5);
    const int lane = threadIdx.x & 31;
    float* srow = g_scores + (size_t)row * K_;

    float4 v0 = *(const float4*)&srow[lane * 4];
    float4 v1 = *(const float4*)&srow[128 + lane * 4];

    float mx = fmaxf(fmaxf(fmaxf(v0.x, v0.y), fmaxf(v0.z, v0.w)),
                     fmaxf(fmaxf(v1.x, v1.y), fmaxf(v1.z, v1.w)));
#pragma unroll
    for (int off = 16; off; off >>= 1)
        mx = fmaxf(mx, __shfl_xor_sync(0xffffffffu, mx, off));

    v0.x = __expf(v0.x - mx); v0.y = __expf(v0.y - mx);
    v0.z = __expf(v0.z - mx); v0.w = __expf(v0.w - mx);
    v1.x = __expf(v1.x - mx); v1.y = __expf(v1.y - mx);
    v1.z = __expf(v1.z - mx); v1.w = __expf(v1.w - mx);

    float s = (v0.x + v0.y + v0.z + v0.w) + (v1.x + v1.y + v1.z + v1.w);
#pragma unroll
    for (int off = 16; off; off >>= 1)
        s += __shfl_xor_sync(0xffffffffu, s, off);
    const float inv = 1.0f / s;

    v0.x *= inv; v0.y *= inv; v0.z *= inv; v0.w *= inv;
    v1.x *= inv; v1.y *= inv; v1.z *= inv; v1.w *= inv;

    *(float4*)&srow[lane * 4] = v0;
    *(float4*)&srow[128 + lane * 4] = v1;
}

// ---------------------------------------------------------------------------
// Kernel 4: AV GEMM  out[m, n] = sum_k P[m,k] * V[b(m)][k,n]
// Same tiling as proj_gemm (measured 11us on identical shape). No transpose
// needed for V (k is the leading row index).
// ---------------------------------------------------------------------------
__global__ __launch_bounds__(256) void av_gemm(const float* __restrict__ V,
                                               float* __restrict__ out) {
    constexpr int BM = 64, BN = 64, BK = 32;
    __shared__ float As[BK][BM + 4];
    __shared__ float Bs[BK][BN + 4];

    const int tid = threadIdx.x;
    const int m0 = blockIdx.y * BM;
    const int n0 = blockIdx.x * BN;
    const int b = m0 >> 8;                      // 256 rows per batch
    const float* __restrict__ P = g_scores;
    const float* __restrict__ Vb = V + (size_t)b * K_ * DV_;

    const int ty = tid >> 4;
    const int tx = tid & 15;
    const int lr = tid >> 3;        // 0..31
    const int lc = (tid & 7) * 4;   // 0..28

    float acc[4][4];
#pragma unroll
    for (int i = 0; i < 4; i++)
#pragma unroll
        for (int j = 0; j < 4; j++) acc[i][j] = 0.0f;

    for (int kt = 0; kt < K_; kt += BK) {
        // P tile (64 x 32), transposed into As[k][m]
        float4 a0 = *(const float4*)&P[(size_t)(m0 + lr) * K_ + kt + lc];
        float4 a1 = *(const float4*)&P[(size_t)(m0 + lr + 32) * K_ + kt + lc];
        // V tile (32 k-rows x 64 cols), direct into Bs[k][n]
        float4 b0 = *(const float4*)&Vb[(size_t)(kt + lr) * DV_ + n0 + lc];
        float4 b1 = *(const float4*)&Vb[(size_t)(kt + lr) * DV_ + n0 + 32 + lc];

        As[lc + 0][lr] = a0.x; As[lc + 1][lr] = a0.y;
        As[lc + 2][lr] = a0.z; As[lc + 3][lr] = a0.w;
        As[lc + 0][lr + 32] = a1.x; As[lc + 1][lr + 32] = a1.y;
        As[lc + 2][lr + 32] = a1.z; As[lc + 3][lr + 32] = a1.w;
        *(float4*)&Bs[lr][lc]      = b0;
        *(float4*)&Bs[lr][lc + 32] = b1;

        __syncthreads();

#pragma unroll
        for (int kk = 0; kk < BK; kk++) {
            float a[4], bb[4];
#pragma unroll
            for (int i = 0; i < 4; i++) a[i] = As[kk][ty * 4 + i];
#pragma unroll
            for (int j = 0; j < 4; j++) bb[j] = Bs[kk][tx * 4 + j];
#pragma unroll
            for (int i = 0; i < 4; i++)
#pragma unroll
                for (int j = 0; j < 4; j++) acc[i][j] += a[i] * bb[j];
        }
        __syncthreads();
    }

#pragma unroll
    for (int i = 0; i < 4; i++) {
        float4 v;
        v.x = acc[i][0]; v.y = acc[i][1]; v.z = acc[i][2]; v.w = acc[i][3];
        *(float4*)&out[(size_t)(m0 + ty * 4 + i) * DV_ + n0 + tx * 4] = v;
    }
}

// ---------------------------------------------------------------------------
extern "C" void kernel_launch(void* const* d_in, const int* in_sizes, int n_in,
                              void* d_out, int out_size) {
    const float* queries = (const float*)d_in[0];
    const float* keys    = (const float*)d_in[1];
    const float* values  = (const float*)d_in[2];
    const float* W_q     = (const float*)d_in[3];
    const float* W_k     = (const float*)d_in[4];
    const float* w_v     = (const float*)d_in[5];
    float* out = (float*)d_out;

    dim3 gproj(H_ / 64, (B_ * Q_) / 64);
    proj_gemm<<<gproj, 256>>>(queries, W_q, 0);
    proj_gemm<<<gproj, 256>>>(keys,    W_k, 1);

    dim3 gscores(K_ / 32, Q_ / 32, B_);
    scores_kernel<<<gscores, 256>>>(w_v);

    softmax_inplace<<<(B_ * Q_) / 8, 256>>>();

    dim3 gav(DV_ / 64, (B_ * Q_) / 64);
    av_gemm<<<gav, 256>>>(values, out);
}